// round 4
// baseline (speedup 1.0000x reference)
#include <cuda_runtime.h>
#include <cuda_bf16.h>
#include <cstdint>

#define NPTS 4096
#define KNB  32
#define BMAX 4

// ---------------- scratch (no cudaMalloc allowed) ----------------
__device__ int   g_idx  [BMAX * NPTS * KNB];
__device__ float g_feat [(size_t)3 * BMAX * NPTS * 128];
__device__ float g_point[(size_t)BMAX * 384  * NPTS];
__device__ float g_gf0  [(size_t)BMAX * 256  * NPTS];
__device__ float g_gf   [(size_t)BMAX * 1024 * NPTS];
__device__ float g_msf0 [(size_t)BMAX * 256  * NPTS];

// =================================================================
// K1: KNN — warp per query. Lane-distributed sorted top-32 list
// (lane 0 = nearest). Chunked candidates + ballot filter + warp
// insertion (only on accept, which is rare after warm-up).
// =================================================================
__global__ __launch_bounds__(256) void knn_kernel(const float* __restrict__ x,
                                                  int* __restrict__ idx)
{
    __shared__ float4 tile[1024];
    const int b = blockIdx.y;
    const int tid = threadIdx.x;
    const int w = tid >> 5, lane = tid & 31;
    const int q = blockIdx.x * 8 + w;
    const float* xb = x + (size_t)b * 3 * NPTS;

    const float qx = xb[q], qy = xb[NPTS + q], qz = xb[2 * NPTS + q];
    const float qsq = qx * qx + qy * qy + qz * qz;

    float v = 3.0e38f;          // my slot's distance (sorted ascending by lane)
    int   vi = 0x7fffffff;      // my slot's index
    float cm = 3.0e38f;         // current worst (lane 31)

    for (int t0 = 0; t0 < NPTS; t0 += 1024) {
        __syncthreads();
        for (int i = tid; i < 1024; i += 256) {
            const int g = t0 + i;
            const float cx = xb[g], cy = xb[NPTS + g], cz = xb[2 * NPTS + g];
            tile[i] = make_float4(cx, cy, cz, cx * cx + cy * cy + cz * cz);
        }
        __syncthreads();

        for (int c = 0; c < 32; c++) {
            const int gbase = t0 + c * 32;
            const float4 p = tile[c * 32 + lane];
            float d = qsq + p.w - 2.0f * fmaf(qx, p.x, fmaf(qy, p.y, qz * p.z));
            if (gbase + lane == q) d = 3.0e38f;   // exclude self

            unsigned m = __ballot_sync(0xffffffffu, d < cm);
            while (m) {
                const int src = __ffs(m) - 1; m &= m - 1;
                const float dd = __shfl_sync(0xffffffffu, d, src);
                const int   ii = gbase + src;
                const unsigned less = __ballot_sync(0xffffffffu,
                        (v < dd) || (v == dd && vi < ii));
                const int pos = __popc(less);
                const float pv = __shfl_up_sync(0xffffffffu, v, 1);
                const int   pi = __shfl_up_sync(0xffffffffu, vi, 1);
                if (pos < 32) {
                    if (lane == pos)      { v = dd; vi = ii; }
                    else if (lane > pos)  { v = pv; vi = pi; }
                }
                cm = __shfl_sync(0xffffffffu, v, 31);
            }
        }
    }
    idx[((size_t)b * NPTS + q) * KNB + lane] = vi;
}

// =================================================================
// K2: per-point 3-layer MLP (3->64->64->128). The neighbor MLP only
// depends on the gathered point, so evaluate ONCE per point per
// scale: feat[s][b][j][128]. 32x less work than per-(n,k).
// thread = one point. grid = (N/128, 3 scales, B)
// =================================================================
#define SMEM_FEAT_FLOATS (192 + 64 + 4096 + 64 + 8192 + 128)
#define SMEM_FEAT_BYTES  (SMEM_FEAT_FLOATS * 4)

__global__ __launch_bounds__(128) void feat_kernel(
    const float* __restrict__ x,
    const float* __restrict__ sW0, const float* __restrict__ sb0,
    const float* __restrict__ sW1, const float* __restrict__ sb1,
    const float* __restrict__ sW2, const float* __restrict__ sb2,
    float* __restrict__ feat, int B)
{
    extern __shared__ float sm[];
    float* w0s = sm;                 // 192
    float* b0s = w0s + 192;          // 64
    float* w1s = b0s + 64;           // 4096
    float* b1s = w1s + 4096;         // 64
    float* w2s = b1s + 64;           // 8192
    float* b2s = w2s + 8192;         // 128

    const int s = blockIdx.y, b = blockIdx.z;
    const int tid = threadIdx.x;

    for (int i = tid; i < 192;  i += 128) w0s[i] = sW0[s * 192 + i];
    for (int i = tid; i < 64;   i += 128) { b0s[i] = sb0[s * 64 + i]; b1s[i] = sb1[s * 64 + i]; }
    for (int i = tid; i < 4096; i += 128) w1s[i] = sW1[s * 4096 + i];
    for (int i = tid; i < 8192; i += 128) w2s[i] = sW2[s * 8192 + i];
    for (int i = tid; i < 128;  i += 128) b2s[i] = sb2[s * 128 + i];
    __syncthreads();

    const int j = blockIdx.x * 128 + tid;
    const float* xb = x + (size_t)b * 3 * NPTS;
    const float px = xb[j], py = xb[NPTS + j], pz = xb[2 * NPTS + j];

    // layer 1: 3 -> 64
    float h0[64];
#pragma unroll
    for (int o = 0; o < 64; o++) {
        float a = fmaf(w0s[o * 3 + 2], pz,
                  fmaf(w0s[o * 3 + 1], py,
                  fmaf(w0s[o * 3 + 0], px, b0s[o])));
        h0[o] = fmaxf(a, 0.0f);
    }

    // layer 2: 64 -> 64
    float h1[64];
#pragma unroll
    for (int o = 0; o < 64; o += 4) {
        float a0 = b1s[o], a1 = b1s[o + 1], a2 = b1s[o + 2], a3 = b1s[o + 3];
        const float4* r0 = (const float4*)(w1s + (o    ) * 64);
        const float4* r1 = (const float4*)(w1s + (o + 1) * 64);
        const float4* r2 = (const float4*)(w1s + (o + 2) * 64);
        const float4* r3 = (const float4*)(w1s + (o + 3) * 64);
#pragma unroll
        for (int c = 0; c < 16; c++) {
            const float x0 = h0[4 * c], x1 = h0[4 * c + 1], x2 = h0[4 * c + 2], x3 = h0[4 * c + 3];
            float4 u;
            u = r0[c]; a0 = fmaf(u.x, x0, a0); a0 = fmaf(u.y, x1, a0); a0 = fmaf(u.z, x2, a0); a0 = fmaf(u.w, x3, a0);
            u = r1[c]; a1 = fmaf(u.x, x0, a1); a1 = fmaf(u.y, x1, a1); a1 = fmaf(u.z, x2, a1); a1 = fmaf(u.w, x3, a1);
            u = r2[c]; a2 = fmaf(u.x, x0, a2); a2 = fmaf(u.y, x1, a2); a2 = fmaf(u.z, x2, a2); a2 = fmaf(u.w, x3, a2);
            u = r3[c]; a3 = fmaf(u.x, x0, a3); a3 = fmaf(u.y, x1, a3); a3 = fmaf(u.z, x2, a3); a3 = fmaf(u.w, x3, a3);
        }
        h1[o] = fmaxf(a0, 0.0f); h1[o + 1] = fmaxf(a1, 0.0f);
        h1[o + 2] = fmaxf(a2, 0.0f); h1[o + 3] = fmaxf(a3, 0.0f);
    }

    // layer 3: 64 -> 128, relu, store
    float* fout = feat + ((size_t)(s * B + b) * NPTS + j) * 128;
    for (int o = 0; o < 128; o += 4) {
        float a0 = b2s[o], a1 = b2s[o + 1], a2 = b2s[o + 2], a3 = b2s[o + 3];
        const float4* r0 = (const float4*)(w2s + (size_t)(o    ) * 64);
        const float4* r1 = (const float4*)(w2s + (size_t)(o + 1) * 64);
        const float4* r2 = (const float4*)(w2s + (size_t)(o + 2) * 64);
        const float4* r3 = (const float4*)(w2s + (size_t)(o + 3) * 64);
#pragma unroll
        for (int c = 0; c < 16; c++) {
            const float x0 = h1[4 * c], x1 = h1[4 * c + 1], x2 = h1[4 * c + 2], x3 = h1[4 * c + 3];
            float4 u;
            u = r0[c]; a0 = fmaf(u.x, x0, a0); a0 = fmaf(u.y, x1, a0); a0 = fmaf(u.z, x2, a0); a0 = fmaf(u.w, x3, a0);
            u = r1[c]; a1 = fmaf(u.x, x0, a1); a1 = fmaf(u.y, x1, a1); a1 = fmaf(u.z, x2, a1); a1 = fmaf(u.w, x3, a1);
            u = r2[c]; a2 = fmaf(u.x, x0, a2); a2 = fmaf(u.y, x1, a2); a2 = fmaf(u.z, x2, a2); a2 = fmaf(u.w, x3, a2);
            u = r3[c]; a3 = fmaf(u.x, x0, a3); a3 = fmaf(u.y, x1, a3); a3 = fmaf(u.z, x2, a3); a3 = fmaf(u.w, x3, a3);
        }
        float4 o4;
        o4.x = fmaxf(a0, 0.0f); o4.y = fmaxf(a1, 0.0f);
        o4.z = fmaxf(a2, 0.0f); o4.w = fmaxf(a3, 0.0f);
        *(float4*)(fout + o) = o4;
    }
}

// =================================================================
// K3: gather-max over 32 neighbors. warp = point, lane = 4 channels.
// point[b][s*128+c][n] = max_k feat[s][b][idx[n][k]][c]
// grid = (N/8, 3, B), block 256
// =================================================================
__global__ __launch_bounds__(256) void maxpool_kernel(
    const float* __restrict__ feat, const int* __restrict__ idx,
    float* __restrict__ point, int B)
{
    __shared__ float obuf[8 * 128];
    const int s = blockIdx.y, b = blockIdx.z;
    const int tid = threadIdx.x;
    const int w = tid >> 5, lane = tid & 31;
    const int n0 = blockIdx.x * 8;
    const int n = n0 + w;

    const int ki = idx[((size_t)b * NPTS + n) * KNB + lane];
    const float* fb = feat + (size_t)(s * B + b) * NPTS * 128;

    float4 m = make_float4(-3.0e38f, -3.0e38f, -3.0e38f, -3.0e38f);
#pragma unroll
    for (int k = 0; k < KNB; k++) {
        const int j = __shfl_sync(0xffffffffu, ki, k);
        const float4 vv = *(const float4*)(fb + (size_t)j * 128 + lane * 4);
        m.x = fmaxf(m.x, vv.x); m.y = fmaxf(m.y, vv.y);
        m.z = fmaxf(m.z, vv.z); m.w = fmaxf(m.w, vv.w);
    }
    *(float4*)(obuf + w * 128 + lane * 4) = m;
    __syncthreads();

    for (int t = tid; t < 1024; t += 256) {
        const int c = t >> 3, p = t & 7;
        point[((size_t)b * 384 + s * 128 + c) * NPTS + n0 + p] = obuf[p * 128 + c];
    }
}

// =================================================================
// K4..: tiled fp32 GEMM, C = relu(W[MxK] @ X[b][KxN] + bias)
// =================================================================
__global__ __launch_bounds__(256) void gemm_bias_relu(
    const float* __restrict__ W, const float* __restrict__ bias,
    const float* __restrict__ X, float* __restrict__ Y, int M, int K)
{
    const int N = NPTS;
    __shared__ __align__(16) float As[8][128];
    __shared__ __align__(16) float Bs[8][128];

    const int b = blockIdx.z;
    const float* Xb = X + (size_t)b * K * N;
    float* Yb = Y + (size_t)b * M * N;
    const int m0 = blockIdx.y * 128, n0 = blockIdx.x * 128;
    const int tid = threadIdx.x;
    const int tx = tid & 15, ty = tid >> 4;

    float acc[8][8];
#pragma unroll
    for (int i = 0; i < 8; i++)
#pragma unroll
        for (int j = 0; j < 8; j++) acc[i][j] = 0.0f;

    for (int k0 = 0; k0 < K; k0 += 8) {
        {
            const int row = tid >> 1;
            const int kq = (tid & 1) << 2;
            const float4 v = *(const float4*)(W + (size_t)(m0 + row) * K + k0 + kq);
            As[kq][row] = v.x; As[kq + 1][row] = v.y; As[kq + 2][row] = v.z; As[kq + 3][row] = v.w;
        }
        {
            const int kk = tid >> 5;
            const int nn = (tid & 31) << 2;
            *(float4*)&Bs[kk][nn] = *(const float4*)(Xb + (size_t)(k0 + kk) * N + n0 + nn);
        }
        __syncthreads();
#pragma unroll
        for (int kk = 0; kk < 8; kk++) {
            float a[8], bb[8];
            *(float4*)(a)     = *(const float4*)&As[kk][ty * 4];
            *(float4*)(a + 4) = *(const float4*)&As[kk][64 + ty * 4];
            *(float4*)(bb)     = *(const float4*)&Bs[kk][tx * 4];
            *(float4*)(bb + 4) = *(const float4*)&Bs[kk][64 + tx * 4];
#pragma unroll
            for (int i = 0; i < 8; i++)
#pragma unroll
                for (int j = 0; j < 8; j++)
                    acc[i][j] = fmaf(a[i], bb[j], acc[i][j]);
        }
        __syncthreads();
    }

#pragma unroll
    for (int i = 0; i < 8; i++) {
        const int r = m0 + ((i < 4) ? (ty * 4 + i) : (64 + ty * 4 + (i - 4)));
        const float bv = bias[r];
        float4 v0, v1;
        v0.x = fmaxf(acc[i][0] + bv, 0.0f); v0.y = fmaxf(acc[i][1] + bv, 0.0f);
        v0.z = fmaxf(acc[i][2] + bv, 0.0f); v0.w = fmaxf(acc[i][3] + bv, 0.0f);
        v1.x = fmaxf(acc[i][4] + bv, 0.0f); v1.y = fmaxf(acc[i][5] + bv, 0.0f);
        v1.z = fmaxf(acc[i][6] + bv, 0.0f); v1.w = fmaxf(acc[i][7] + bv, 0.0f);
        *(float4*)(Yb + (size_t)r * N + n0 + tx * 4)      = v0;
        *(float4*)(Yb + (size_t)r * N + n0 + 64 + tx * 4) = v1;
    }
}

// =================================================================
// global max over N per (b, channel) of gf
// =================================================================
__global__ __launch_bounds__(128) void rowmax_kernel(const float* __restrict__ gf,
                                                     float* __restrict__ out)
{
    const int o = blockIdx.x, b = blockIdx.y;
    const float* row = gf + ((size_t)b * 1024 + o) * NPTS;
    float m = -3.0e38f;
    for (int i = threadIdx.x; i < NPTS; i += 128) m = fmaxf(m, row[i]);
#pragma unroll
    for (int off = 16; off > 0; off >>= 1) m = fmaxf(m, __shfl_xor_sync(0xffffffffu, m, off));
    __shared__ float smx[4];
    if ((threadIdx.x & 31) == 0) smx[threadIdx.x >> 5] = m;
    __syncthreads();
    if (threadIdx.x == 0)
        out[(size_t)b * 1024 + o] = fmaxf(fmaxf(smx[0], smx[1]), fmaxf(smx[2], smx[3]));
}

// =================================================================
extern "C" void kernel_launch(void* const* d_in, const int* in_sizes, int n_in,
                              void* d_out, int out_size)
{
    const float* x   = (const float*)d_in[0];
    const float* sW0 = (const float*)d_in[1];
    const float* sb0 = (const float*)d_in[2];
    const float* sW1 = (const float*)d_in[3];
    const float* sb1 = (const float*)d_in[4];
    const float* sW2 = (const float*)d_in[5];
    const float* sb2 = (const float*)d_in[6];
    const float* gW0 = (const float*)d_in[7];
    const float* gb0 = (const float*)d_in[8];
    const float* gW1 = (const float*)d_in[9];
    const float* gb1 = (const float*)d_in[10];
    const float* mW0 = (const float*)d_in[11];
    const float* mb0 = (const float*)d_in[12];
    const float* mW1 = (const float*)d_in[13];
    const float* mb1 = (const float*)d_in[14];

    const int B = in_sizes[0] / (3 * NPTS);
    float* out = (float*)d_out;

    void *p_idx, *p_feat, *p_point, *p_gf0, *p_gf, *p_msf0;
    cudaGetSymbolAddress(&p_idx,   g_idx);
    cudaGetSymbolAddress(&p_feat,  g_feat);
    cudaGetSymbolAddress(&p_point, g_point);
    cudaGetSymbolAddress(&p_gf0,   g_gf0);
    cudaGetSymbolAddress(&p_gf,    g_gf);
    cudaGetSymbolAddress(&p_msf0,  g_msf0);

    cudaFuncSetAttribute(feat_kernel,
                         cudaFuncAttributeMaxDynamicSharedMemorySize, SMEM_FEAT_BYTES);

    // 1) KNN (warp per query)
    knn_kernel<<<dim3(NPTS / 8, B), 256>>>(x, (int*)p_idx);

    // 2) per-point MLP features: feat[s][b][j][128]
    feat_kernel<<<dim3(NPTS / 128, 3, B), 128, SMEM_FEAT_BYTES>>>(
        x, sW0, sb0, sW1, sb1, sW2, sb2, (float*)p_feat, B);

    // 3) gather-max over neighbors -> point[B,384,N]
    maxpool_kernel<<<dim3(NPTS / 8, 3, B), 256>>>(
        (const float*)p_feat, (const int*)p_idx, (float*)p_point, B);

    // 4) gf0 = relu(gW0 @ point + gb0)   [B,256,N]
    gemm_bias_relu<<<dim3(NPTS / 128, 256 / 128, B), 256>>>(
        gW0, gb0, (const float*)p_point, (float*)p_gf0, 256, 384);

    // 5) gf = relu(gW1 @ gf0 + gb1)      [B,1024,N]
    gemm_bias_relu<<<dim3(NPTS / 128, 1024 / 128, B), 256>>>(
        gW1, gb1, (const float*)p_gf0, (float*)p_gf, 1024, 256);

    // 6) global_feature = max_n gf -> d_out[0 : B*1024]
    rowmax_kernel<<<dim3(1024, B), 128>>>((const float*)p_gf, out);

    // 7) msf0 = relu(mW0 @ gf + mb0)     [B,256,N]
    gemm_bias_relu<<<dim3(NPTS / 128, 256 / 128, B), 256>>>(
        mW0, mb0, (const float*)p_gf, (float*)p_msf0, 256, 1024);

    // 8) msf = relu(mW1 @ msf0 + mb1) -> d_out[B*1024 : ]
    gemm_bias_relu<<<dim3(NPTS / 128, 128 / 128, B), 256>>>(
        mW1, mb1, (const float*)p_msf0, out + (size_t)B * 1024, 128, 256);
}

// round 5
// speedup vs baseline: 1.0322x; 1.0322x over previous
#include <cuda_runtime.h>
#include <cuda_bf16.h>
#include <cstdint>

#define NPTS 4096
#define KNB  32
#define BMAX 4

typedef unsigned long long ull;

// ---------------- f32x2 packed-FMA helpers (exact fp32) ----------------
__device__ __forceinline__ ull pack2(float lo, float hi) {
    ull r; asm("mov.b64 %0, {%1, %2};" : "=l"(r) : "f"(lo), "f"(hi)); return r;
}
__device__ __forceinline__ ull dup2(float v) { return pack2(v, v); }
__device__ __forceinline__ ull ffma2(ull a, ull b, ull c) {
    ull d; asm("fma.rn.f32x2 %0, %1, %2, %3;" : "=l"(d) : "l"(a), "l"(b), "l"(c));
    return d;
}
__device__ __forceinline__ float2 unpack2(ull v) {
    float lo, hi; asm("mov.b64 {%0, %1}, %2;" : "=f"(lo), "=f"(hi) : "l"(v));
    return make_float2(lo, hi);
}

// ---------------- scratch (no cudaMalloc allowed) ----------------
__device__ int   g_idx  [BMAX * NPTS * KNB];
__device__ float g_feat [(size_t)3 * BMAX * NPTS * 128];
__device__ float g_point[(size_t)BMAX * 384  * NPTS];
__device__ float g_gf0  [(size_t)BMAX * 256  * NPTS];
__device__ float g_gf   [(size_t)BMAX * 1024 * NPTS];
__device__ float g_msf0 [(size_t)BMAX * 256  * NPTS];

// =================================================================
// K1: KNN — warp per query, lane-distributed sorted top-32 list
// =================================================================
__global__ __launch_bounds__(256) void knn_kernel(const float* __restrict__ x,
                                                  int* __restrict__ idx)
{
    __shared__ float4 tile[1024];
    const int b = blockIdx.y;
    const int tid = threadIdx.x;
    const int w = tid >> 5, lane = tid & 31;
    const int q = blockIdx.x * 8 + w;
    const float* xb = x + (size_t)b * 3 * NPTS;

    const float qx = xb[q], qy = xb[NPTS + q], qz = xb[2 * NPTS + q];
    const float qsq = qx * qx + qy * qy + qz * qz;

    float v = 3.0e38f;
    int   vi = 0x7fffffff;
    float cm = 3.0e38f;

    for (int t0 = 0; t0 < NPTS; t0 += 1024) {
        __syncthreads();
        for (int i = tid; i < 1024; i += 256) {
            const int g = t0 + i;
            const float cx = xb[g], cy = xb[NPTS + g], cz = xb[2 * NPTS + g];
            tile[i] = make_float4(cx, cy, cz, cx * cx + cy * cy + cz * cz);
        }
        __syncthreads();

        for (int c = 0; c < 32; c++) {
            const int gbase = t0 + c * 32;
            const float4 p = tile[c * 32 + lane];
            float d = qsq + p.w - 2.0f * fmaf(qx, p.x, fmaf(qy, p.y, qz * p.z));
            if (gbase + lane == q) d = 3.0e38f;

            unsigned m = __ballot_sync(0xffffffffu, d < cm);
            while (m) {
                const int src = __ffs(m) - 1; m &= m - 1;
                const float dd = __shfl_sync(0xffffffffu, d, src);
                const int   ii = gbase + src;
                const unsigned less = __ballot_sync(0xffffffffu,
                        (v < dd) || (v == dd && vi < ii));
                const int pos = __popc(less);
                const float pv = __shfl_up_sync(0xffffffffu, v, 1);
                const int   pi = __shfl_up_sync(0xffffffffu, vi, 1);
                if (pos < 32) {
                    if (lane == pos)      { v = dd; vi = ii; }
                    else if (lane > pos)  { v = pv; vi = pi; }
                }
                cm = __shfl_sync(0xffffffffu, v, 31);
            }
        }
    }
    idx[((size_t)b * NPTS + q) * KNB + lane] = vi;
}

// =================================================================
// K2: per-point 3-layer MLP (3->64->64->128), f32x2 packed math.
// thread = one point. grid = (N/128, 3 scales, B)
// =================================================================
#define SMEM_FEAT_FLOATS (192 + 64 + 4096 + 64 + 8192 + 128)
#define SMEM_FEAT_BYTES  (SMEM_FEAT_FLOATS * 4)

__global__ __launch_bounds__(128) void feat_kernel(
    const float* __restrict__ x,
    const float* __restrict__ sW0, const float* __restrict__ sb0,
    const float* __restrict__ sW1, const float* __restrict__ sb1,
    const float* __restrict__ sW2, const float* __restrict__ sb2,
    float* __restrict__ feat, int B)
{
    extern __shared__ float sm[];
    float* w0s = sm;                 // 192
    float* b0s = w0s + 192;          // 64
    float* w1s = b0s + 64;           // 4096
    float* b1s = w1s + 4096;         // 64
    float* w2s = b1s + 64;           // 8192
    float* b2s = w2s + 8192;         // 128

    const int s = blockIdx.y, b = blockIdx.z;
    const int tid = threadIdx.x;

    for (int i = tid; i < 192;  i += 128) w0s[i] = sW0[s * 192 + i];
    for (int i = tid; i < 64;   i += 128) { b0s[i] = sb0[s * 64 + i]; b1s[i] = sb1[s * 64 + i]; }
    for (int i = tid; i < 4096; i += 128) w1s[i] = sW1[s * 4096 + i];
    for (int i = tid; i < 8192; i += 128) w2s[i] = sW2[s * 8192 + i];
    for (int i = tid; i < 128;  i += 128) b2s[i] = sb2[s * 128 + i];
    __syncthreads();

    const int j = blockIdx.x * 128 + tid;
    const float* xb = x + (size_t)b * 3 * NPTS;
    const float px = xb[j], py = xb[NPTS + j], pz = xb[2 * NPTS + j];

    // ---- layer 1: 3 -> 64 (scalar) ----
    float h0[64];
#pragma unroll
    for (int o = 0; o < 64; o++) {
        float a = fmaf(w0s[o * 3 + 2], pz,
                  fmaf(w0s[o * 3 + 1], py,
                  fmaf(w0s[o * 3 + 0], px, b0s[o])));
        h0[o] = fmaxf(a, 0.0f);
    }

    // ---- layer 2: 64 -> 64, packed pairs along input dim ----
    ull hp[32];
#pragma unroll
    for (int c = 0; c < 32; c++) hp[c] = pack2(h0[2 * c], h0[2 * c + 1]);

    float h1[64];
#pragma unroll
    for (int o = 0; o < 64; o += 2) {
        ull a0 = 0ull, a1 = 0ull;   // (0.0f, 0.0f)
        const ull* r0 = (const ull*)(w1s + (o    ) * 64);
        const ull* r1 = (const ull*)(w1s + (o + 1) * 64);
#pragma unroll
        for (int c = 0; c < 32; c++) {
            a0 = ffma2(r0[c], hp[c], a0);
            a1 = ffma2(r1[c], hp[c], a1);
        }
        const float2 u0 = unpack2(a0), u1 = unpack2(a1);
        h1[o]     = fmaxf(u0.x + u0.y + b1s[o],     0.0f);
        h1[o + 1] = fmaxf(u1.x + u1.y + b1s[o + 1], 0.0f);
    }

    // ---- layer 3: 64 -> 128, packed ----
#pragma unroll
    for (int c = 0; c < 32; c++) hp[c] = pack2(h1[2 * c], h1[2 * c + 1]);

    float* fout = feat + ((size_t)(s * B + b) * NPTS + j) * 128;
    for (int o = 0; o < 128; o += 4) {
        ull a0 = 0ull, a1 = 0ull, a2 = 0ull, a3 = 0ull;
        const ull* r0 = (const ull*)(w2s + (size_t)(o    ) * 64);
        const ull* r1 = (const ull*)(w2s + (size_t)(o + 1) * 64);
        const ull* r2 = (const ull*)(w2s + (size_t)(o + 2) * 64);
        const ull* r3 = (const ull*)(w2s + (size_t)(o + 3) * 64);
#pragma unroll
        for (int c = 0; c < 32; c++) {
            a0 = ffma2(r0[c], hp[c], a0);
            a1 = ffma2(r1[c], hp[c], a1);
            a2 = ffma2(r2[c], hp[c], a2);
            a3 = ffma2(r3[c], hp[c], a3);
        }
        const float2 u0 = unpack2(a0), u1 = unpack2(a1);
        const float2 u2 = unpack2(a2), u3 = unpack2(a3);
        float4 o4;
        o4.x = fmaxf(u0.x + u0.y + b2s[o],     0.0f);
        o4.y = fmaxf(u1.x + u1.y + b2s[o + 1], 0.0f);
        o4.z = fmaxf(u2.x + u2.y + b2s[o + 2], 0.0f);
        o4.w = fmaxf(u3.x + u3.y + b2s[o + 3], 0.0f);
        *(float4*)(fout + o) = o4;
    }
}

// =================================================================
// K3: gather-max over 32 neighbors. warp = point, lane = 4 channels.
// =================================================================
__global__ __launch_bounds__(256) void maxpool_kernel(
    const float* __restrict__ feat, const int* __restrict__ idx,
    float* __restrict__ point, int B)
{
    __shared__ float obuf[8 * 128];
    const int s = blockIdx.y, b = blockIdx.z;
    const int tid = threadIdx.x;
    const int w = tid >> 5, lane = tid & 31;
    const int n0 = blockIdx.x * 8;
    const int n = n0 + w;

    const int ki = idx[((size_t)b * NPTS + n) * KNB + lane];
    const float* fb = feat + (size_t)(s * B + b) * NPTS * 128;

    float4 m = make_float4(-3.0e38f, -3.0e38f, -3.0e38f, -3.0e38f);
#pragma unroll
    for (int k = 0; k < KNB; k++) {
        const int j = __shfl_sync(0xffffffffu, ki, k);
        const float4 vv = *(const float4*)(fb + (size_t)j * 128 + lane * 4);
        m.x = fmaxf(m.x, vv.x); m.y = fmaxf(m.y, vv.y);
        m.z = fmaxf(m.z, vv.z); m.w = fmaxf(m.w, vv.w);
    }
    *(float4*)(obuf + w * 128 + lane * 4) = m;
    __syncthreads();

    for (int t = tid; t < 1024; t += 256) {
        const int c = t >> 3, p = t & 7;
        point[((size_t)b * 384 + s * 128 + c) * NPTS + n0 + p] = obuf[p * 128 + c];
    }
}

// =================================================================
// K4..: tiled fp32 GEMM with f32x2 packed FMA.
// C = relu(W[MxK] @ X[b][KxN] + bias), 128x128 tile, 8x8/thread.
// =================================================================
__global__ __launch_bounds__(256) void gemm_bias_relu(
    const float* __restrict__ W, const float* __restrict__ bias,
    const float* __restrict__ X, float* __restrict__ Y, int M, int K)
{
    const int N = NPTS;
    __shared__ __align__(16) float As[8][128];
    __shared__ __align__(16) float Bs[8][128];

    const int b = blockIdx.z;
    const float* Xb = X + (size_t)b * K * N;
    float* Yb = Y + (size_t)b * M * N;
    const int m0 = blockIdx.y * 128, n0 = blockIdx.x * 128;
    const int tid = threadIdx.x;
    const int tx = tid & 15, ty = tid >> 4;

    // acc2[i][p]: row i (8 rows), p = column pair
    // p=0: (tx*4, tx*4+1)   p=1: (tx*4+2, tx*4+3)
    // p=2: (64+tx*4, +1)    p=3: (64+tx*4+2, +3)
    ull acc2[8][4];
#pragma unroll
    for (int i = 0; i < 8; i++)
#pragma unroll
        for (int p = 0; p < 4; p++) acc2[i][p] = 0ull;

    for (int k0 = 0; k0 < K; k0 += 8) {
        {   // A tile: 128 rows x 8 k
            const int row = tid >> 1;
            const int kq = (tid & 1) << 2;
            const float4 v = *(const float4*)(W + (size_t)(m0 + row) * K + k0 + kq);
            As[kq][row] = v.x; As[kq + 1][row] = v.y; As[kq + 2][row] = v.z; As[kq + 3][row] = v.w;
        }
        {   // B tile: 8 k x 128 n
            const int kk = tid >> 5;
            const int nn = (tid & 31) << 2;
            *(float4*)&Bs[kk][nn] = *(const float4*)(Xb + (size_t)(k0 + kk) * N + n0 + nn);
        }
        __syncthreads();
#pragma unroll
        for (int kk = 0; kk < 8; kk++) {
            float a[8];
            *(float4*)(a)     = *(const float4*)&As[kk][ty * 4];
            *(float4*)(a + 4) = *(const float4*)&As[kk][64 + ty * 4];
            ull b2[4];
            {
                const ull* pb0 = (const ull*)&Bs[kk][tx * 4];
                const ull* pb1 = (const ull*)&Bs[kk][64 + tx * 4];
                b2[0] = pb0[0]; b2[1] = pb0[1];
                b2[2] = pb1[0]; b2[3] = pb1[1];
            }
            ull ad[8];
#pragma unroll
            for (int i = 0; i < 8; i++) ad[i] = dup2(a[i]);
#pragma unroll
            for (int i = 0; i < 8; i++)
#pragma unroll
                for (int p = 0; p < 4; p++)
                    acc2[i][p] = ffma2(ad[i], b2[p], acc2[i][p]);
        }
        __syncthreads();
    }

#pragma unroll
    for (int i = 0; i < 8; i++) {
        const int r = m0 + ((i < 4) ? (ty * 4 + i) : (64 + ty * 4 + (i - 4)));
        const float bv = bias[r];
        const float2 c0 = unpack2(acc2[i][0]), c1 = unpack2(acc2[i][1]);
        const float2 c2 = unpack2(acc2[i][2]), c3 = unpack2(acc2[i][3]);
        float4 v0, v1;
        v0.x = fmaxf(c0.x + bv, 0.0f); v0.y = fmaxf(c0.y + bv, 0.0f);
        v0.z = fmaxf(c1.x + bv, 0.0f); v0.w = fmaxf(c1.y + bv, 0.0f);
        v1.x = fmaxf(c2.x + bv, 0.0f); v1.y = fmaxf(c2.y + bv, 0.0f);
        v1.z = fmaxf(c3.x + bv, 0.0f); v1.w = fmaxf(c3.y + bv, 0.0f);
        *(float4*)(Yb + (size_t)r * N + n0 + tx * 4)      = v0;
        *(float4*)(Yb + (size_t)r * N + n0 + 64 + tx * 4) = v1;
    }
}

// =================================================================
// global max over N per (b, channel) of gf
// =================================================================
__global__ __launch_bounds__(128) void rowmax_kernel(const float* __restrict__ gf,
                                                     float* __restrict__ out)
{
    const int o = blockIdx.x, b = blockIdx.y;
    const float* row = gf + ((size_t)b * 1024 + o) * NPTS;
    float m = -3.0e38f;
    for (int i = threadIdx.x; i < NPTS; i += 128) m = fmaxf(m, row[i]);
#pragma unroll
    for (int off = 16; off > 0; off >>= 1) m = fmaxf(m, __shfl_xor_sync(0xffffffffu, m, off));
    __shared__ float smx[4];
    if ((threadIdx.x & 31) == 0) smx[threadIdx.x >> 5] = m;
    __syncthreads();
    if (threadIdx.x == 0)
        out[(size_t)b * 1024 + o] = fmaxf(fmaxf(smx[0], smx[1]), fmaxf(smx[2], smx[3]));
}

// =================================================================
extern "C" void kernel_launch(void* const* d_in, const int* in_sizes, int n_in,
                              void* d_out, int out_size)
{
    const float* x   = (const float*)d_in[0];
    const float* sW0 = (const float*)d_in[1];
    const float* sb0 = (const float*)d_in[2];
    const float* sW1 = (const float*)d_in[3];
    const float* sb1 = (const float*)d_in[4];
    const float* sW2 = (const float*)d_in[5];
    const float* sb2 = (const float*)d_in[6];
    const float* gW0 = (const float*)d_in[7];
    const float* gb0 = (const float*)d_in[8];
    const float* gW1 = (const float*)d_in[9];
    const float* gb1 = (const float*)d_in[10];
    const float* mW0 = (const float*)d_in[11];
    const float* mb0 = (const float*)d_in[12];
    const float* mW1 = (const float*)d_in[13];
    const float* mb1 = (const float*)d_in[14];

    const int B = in_sizes[0] / (3 * NPTS);
    float* out = (float*)d_out;

    void *p_idx, *p_feat, *p_point, *p_gf0, *p_gf, *p_msf0;
    cudaGetSymbolAddress(&p_idx,   g_idx);
    cudaGetSymbolAddress(&p_feat,  g_feat);
    cudaGetSymbolAddress(&p_point, g_point);
    cudaGetSymbolAddress(&p_gf0,   g_gf0);
    cudaGetSymbolAddress(&p_gf,    g_gf);
    cudaGetSymbolAddress(&p_msf0,  g_msf0);

    cudaFuncSetAttribute(feat_kernel,
                         cudaFuncAttributeMaxDynamicSharedMemorySize, SMEM_FEAT_BYTES);

    // 1) KNN
    knn_kernel<<<dim3(NPTS / 8, B), 256>>>(x, (int*)p_idx);

    // 2) per-point MLP features
    feat_kernel<<<dim3(NPTS / 128, 3, B), 128, SMEM_FEAT_BYTES>>>(
        x, sW0, sb0, sW1, sb1, sW2, sb2, (float*)p_feat, B);

    // 3) gather-max -> point[B,384,N]
    maxpool_kernel<<<dim3(NPTS / 8, 3, B), 256>>>(
        (const float*)p_feat, (const int*)p_idx, (float*)p_point, B);

    // 4) gf0 = relu(gW0 @ point + gb0)
    gemm_bias_relu<<<dim3(NPTS / 128, 256 / 128, B), 256>>>(
        gW0, gb0, (const float*)p_point, (float*)p_gf0, 256, 384);

    // 5) gf = relu(gW1 @ gf0 + gb1)
    gemm_bias_relu<<<dim3(NPTS / 128, 1024 / 128, B), 256>>>(
        gW1, gb1, (const float*)p_gf0, (float*)p_gf, 1024, 256);

    // 6) global_feature
    rowmax_kernel<<<dim3(1024, B), 128>>>((const float*)p_gf, out);

    // 7) msf0 = relu(mW0 @ gf + mb0)
    gemm_bias_relu<<<dim3(NPTS / 128, 256 / 128, B), 256>>>(
        mW0, mb0, (const float*)p_gf, (float*)p_msf0, 256, 1024);

    // 8) msf = relu(mW1 @ msf0 + mb1)
    gemm_bias_relu<<<dim3(NPTS / 128, 128 / 128, B), 256>>>(
        mW1, mb1, (const float*)p_msf0, out + (size_t)B * 1024, 128, 256);
}

// round 6
// speedup vs baseline: 1.0377x; 1.0053x over previous
#include <cuda_runtime.h>
#include <cuda_bf16.h>
#include <cstdint>

#define NPTS 4096
#define KNB  32
#define BMAX 4

typedef unsigned long long ull;

// ---------------- f32x2 packed-FMA helpers (exact fp32) ----------------
__device__ __forceinline__ ull pack2(float lo, float hi) {
    ull r; asm("mov.b64 %0, {%1, %2};" : "=l"(r) : "f"(lo), "f"(hi)); return r;
}
__device__ __forceinline__ ull dup2(float v) { return pack2(v, v); }
__device__ __forceinline__ ull ffma2(ull a, ull b, ull c) {
    ull d; asm("fma.rn.f32x2 %0, %1, %2, %3;" : "=l"(d) : "l"(a), "l"(b), "l"(c));
    return d;
}
__device__ __forceinline__ float2 unpack2(ull v) {
    float lo, hi; asm("mov.b64 {%0, %1}, %2;" : "=f"(lo), "=f"(hi) : "l"(v));
    return make_float2(lo, hi);
}

// ---------------- scratch (no cudaMalloc allowed) ----------------
__device__ int   g_idx  [BMAX * NPTS * KNB];
__device__ float g_feat [(size_t)3 * BMAX * NPTS * 128];
__device__ float g_point[(size_t)BMAX * 384  * NPTS];
__device__ float g_gf0  [(size_t)BMAX * 256  * NPTS];
__device__ float g_gf   [(size_t)BMAX * 1024 * NPTS];
__device__ float g_msf0 [(size_t)BMAX * 256  * NPTS];

// =================================================================
// K1: KNN — warp per query, lane-distributed sorted top-32 list
// =================================================================
__global__ __launch_bounds__(256) void knn_kernel(const float* __restrict__ x,
                                                  int* __restrict__ idx)
{
    __shared__ float4 tile[1024];
    const int b = blockIdx.y;
    const int tid = threadIdx.x;
    const int w = tid >> 5, lane = tid & 31;
    const int q = blockIdx.x * 8 + w;
    const float* xb = x + (size_t)b * 3 * NPTS;

    const float qx = xb[q], qy = xb[NPTS + q], qz = xb[2 * NPTS + q];
    const float qsq = qx * qx + qy * qy + qz * qz;

    float v = 3.0e38f;
    int   vi = 0x7fffffff;
    float cm = 3.0e38f;

    for (int t0 = 0; t0 < NPTS; t0 += 1024) {
        __syncthreads();
        for (int i = tid; i < 1024; i += 256) {
            const int g = t0 + i;
            const float cx = xb[g], cy = xb[NPTS + g], cz = xb[2 * NPTS + g];
            tile[i] = make_float4(cx, cy, cz, cx * cx + cy * cy + cz * cz);
        }
        __syncthreads();

        for (int c = 0; c < 32; c++) {
            const int gbase = t0 + c * 32;
            const float4 p = tile[c * 32 + lane];
            float d = qsq + p.w - 2.0f * fmaf(qx, p.x, fmaf(qy, p.y, qz * p.z));
            if (gbase + lane == q) d = 3.0e38f;

            unsigned m = __ballot_sync(0xffffffffu, d < cm);
            while (m) {
                const int src = __ffs(m) - 1; m &= m - 1;
                const float dd = __shfl_sync(0xffffffffu, d, src);
                const int   ii = gbase + src;
                const unsigned less = __ballot_sync(0xffffffffu,
                        (v < dd) || (v == dd && vi < ii));
                const int pos = __popc(less);
                const float pv = __shfl_up_sync(0xffffffffu, v, 1);
                const int   pi = __shfl_up_sync(0xffffffffu, vi, 1);
                if (pos < 32) {
                    if (lane == pos)      { v = dd; vi = ii; }
                    else if (lane > pos)  { v = pv; vi = pi; }
                }
                cm = __shfl_sync(0xffffffffu, v, 31);
            }
        }
    }
    idx[((size_t)b * NPTS + q) * KNB + lane] = vi;
}

// =================================================================
// K2: per-point 3-layer MLP (3->64->64->128), f32x2 packed math.
// thread = one point. grid = (N/128, 3 scales, B)
// =================================================================
#define SMEM_FEAT_FLOATS (192 + 64 + 4096 + 64 + 8192 + 128)
#define SMEM_FEAT_BYTES  (SMEM_FEAT_FLOATS * 4)

__global__ __launch_bounds__(128) void feat_kernel(
    const float* __restrict__ x,
    const float* __restrict__ sW0, const float* __restrict__ sb0,
    const float* __restrict__ sW1, const float* __restrict__ sb1,
    const float* __restrict__ sW2, const float* __restrict__ sb2,
    float* __restrict__ feat, int B)
{
    extern __shared__ float sm[];
    float* w0s = sm;                 // 192
    float* b0s = w0s + 192;          // 64
    float* w1s = b0s + 64;           // 4096
    float* b1s = w1s + 4096;         // 64
    float* w2s = b1s + 64;           // 8192
    float* b2s = w2s + 8192;         // 128

    const int s = blockIdx.y, b = blockIdx.z;
    const int tid = threadIdx.x;

    for (int i = tid; i < 192;  i += 128) w0s[i] = sW0[s * 192 + i];
    for (int i = tid; i < 64;   i += 128) { b0s[i] = sb0[s * 64 + i]; b1s[i] = sb1[s * 64 + i]; }
    for (int i = tid; i < 4096; i += 128) w1s[i] = sW1[s * 4096 + i];
    for (int i = tid; i < 8192; i += 128) w2s[i] = sW2[s * 8192 + i];
    for (int i = tid; i < 128;  i += 128) b2s[i] = sb2[s * 128 + i];
    __syncthreads();

    const int j = blockIdx.x * 128 + tid;
    const float* xb = x + (size_t)b * 3 * NPTS;
    const float px = xb[j], py = xb[NPTS + j], pz = xb[2 * NPTS + j];

    // ---- layer 1: 3 -> 64 (scalar) ----
    float h0[64];
#pragma unroll
    for (int o = 0; o < 64; o++) {
        float a = fmaf(w0s[o * 3 + 2], pz,
                  fmaf(w0s[o * 3 + 1], py,
                  fmaf(w0s[o * 3 + 0], px, b0s[o])));
        h0[o] = fmaxf(a, 0.0f);
    }

    // ---- layer 2: 64 -> 64, packed pairs along input dim ----
    ull hp[32];
#pragma unroll
    for (int c = 0; c < 32; c++) hp[c] = pack2(h0[2 * c], h0[2 * c + 1]);

    float h1[64];
#pragma unroll
    for (int o = 0; o < 64; o += 2) {
        ull a0 = 0ull, a1 = 0ull;   // (0.0f, 0.0f)
        const ull* r0 = (const ull*)(w1s + (o    ) * 64);
        const ull* r1 = (const ull*)(w1s + (o + 1) * 64);
#pragma unroll
        for (int c = 0; c < 32; c++) {
            a0 = ffma2(r0[c], hp[c], a0);
            a1 = ffma2(r1[c], hp[c], a1);
        }
        const float2 u0 = unpack2(a0), u1 = unpack2(a1);
        h1[o]     = fmaxf(u0.x + u0.y + b1s[o],     0.0f);
        h1[o + 1] = fmaxf(u1.x + u1.y + b1s[o + 1], 0.0f);
    }

    // ---- layer 3: 64 -> 128, packed ----
#pragma unroll
    for (int c = 0; c < 32; c++) hp[c] = pack2(h1[2 * c], h1[2 * c + 1]);

    float* fout = feat + ((size_t)(s * B + b) * NPTS + j) * 128;
    for (int o = 0; o < 128; o += 4) {
        ull a0 = 0ull, a1 = 0ull, a2 = 0ull, a3 = 0ull;
        const ull* r0 = (const ull*)(w2s + (size_t)(o    ) * 64);
        const ull* r1 = (const ull*)(w2s + (size_t)(o + 1) * 64);
        const ull* r2 = (const ull*)(w2s + (size_t)(o + 2) * 64);
        const ull* r3 = (const ull*)(w2s + (size_t)(o + 3) * 64);
#pragma unroll
        for (int c = 0; c < 32; c++) {
            a0 = ffma2(r0[c], hp[c], a0);
            a1 = ffma2(r1[c], hp[c], a1);
            a2 = ffma2(r2[c], hp[c], a2);
            a3 = ffma2(r3[c], hp[c], a3);
        }
        const float2 u0 = unpack2(a0), u1 = unpack2(a1);
        const float2 u2 = unpack2(a2), u3 = unpack2(a3);
        float4 o4;
        o4.x = fmaxf(u0.x + u0.y + b2s[o],     0.0f);
        o4.y = fmaxf(u1.x + u1.y + b2s[o + 1], 0.0f);
        o4.z = fmaxf(u2.x + u2.y + b2s[o + 2], 0.0f);
        o4.w = fmaxf(u3.x + u3.y + b2s[o + 3], 0.0f);
        *(float4*)(fout + o) = o4;
    }
}

// =================================================================
// K3: gather-max over 32 neighbors. warp = point, lane = 4 channels.
// =================================================================
__global__ __launch_bounds__(256) void maxpool_kernel(
    const float* __restrict__ feat, const int* __restrict__ idx,
    float* __restrict__ point, int B)
{
    __shared__ float obuf[8 * 128];
    const int s = blockIdx.y, b = blockIdx.z;
    const int tid = threadIdx.x;
    const int w = tid >> 5, lane = tid & 31;
    const int n0 = blockIdx.x * 8;
    const int n = n0 + w;

    const int ki = idx[((size_t)b * NPTS + n) * KNB + lane];
    const float* fb = feat + (size_t)(s * B + b) * NPTS * 128;

    float4 m = make_float4(-3.0e38f, -3.0e38f, -3.0e38f, -3.0e38f);
#pragma unroll
    for (int k = 0; k < KNB; k++) {
        const int j = __shfl_sync(0xffffffffu, ki, k);
        const float4 vv = *(const float4*)(fb + (size_t)j * 128 + lane * 4);
        m.x = fmaxf(m.x, vv.x); m.y = fmaxf(m.y, vv.y);
        m.z = fmaxf(m.z, vv.z); m.w = fmaxf(m.w, vv.w);
    }
    *(float4*)(obuf + w * 128 + lane * 4) = m;
    __syncthreads();

    for (int t = tid; t < 1024; t += 256) {
        const int c = t >> 3, p = t & 7;
        point[((size_t)b * 384 + s * 128 + c) * NPTS + n0 + p] = obuf[p * 128 + c];
    }
}

// =================================================================
// K4..: tiled fp32 GEMM with f32x2 packed FMA.
// C = relu(W[MxK] @ X[b][KxN] + bias), 128x128 tile, 8x8/thread.
// =================================================================
__global__ __launch_bounds__(256) void gemm_bias_relu(
    const float* __restrict__ W, const float* __restrict__ bias,
    const float* __restrict__ X, float* __restrict__ Y, int M, int K)
{
    const int N = NPTS;
    __shared__ __align__(16) float As[8][128];
    __shared__ __align__(16) float Bs[8][128];

    const int b = blockIdx.z;
    const float* Xb = X + (size_t)b * K * N;
    float* Yb = Y + (size_t)b * M * N;
    const int m0 = blockIdx.y * 128, n0 = blockIdx.x * 128;
    const int tid = threadIdx.x;
    const int tx = tid & 15, ty = tid >> 4;

    // acc2[i][p]: row i (8 rows), p = column pair
    // p=0: (tx*4, tx*4+1)   p=1: (tx*4+2, tx*4+3)
    // p=2: (64+tx*4, +1)    p=3: (64+tx*4+2, +3)
    ull acc2[8][4];
#pragma unroll
    for (int i = 0; i < 8; i++)
#pragma unroll
        for (int p = 0; p < 4; p++) acc2[i][p] = 0ull;

    for (int k0 = 0; k0 < K; k0 += 8) {
        {   // A tile: 128 rows x 8 k
            const int row = tid >> 1;
            const int kq = (tid & 1) << 2;
            const float4 v = *(const float4*)(W + (size_t)(m0 + row) * K + k0 + kq);
            As[kq][row] = v.x; As[kq + 1][row] = v.y; As[kq + 2][row] = v.z; As[kq + 3][row] = v.w;
        }
        {   // B tile: 8 k x 128 n
            const int kk = tid >> 5;
            const int nn = (tid & 31) << 2;
            *(float4*)&Bs[kk][nn] = *(const float4*)(Xb + (size_t)(k0 + kk) * N + n0 + nn);
        }
        __syncthreads();
#pragma unroll
        for (int kk = 0; kk < 8; kk++) {
            float a[8];
            *(float4*)(a)     = *(const float4*)&As[kk][ty * 4];
            *(float4*)(a + 4) = *(const float4*)&As[kk][64 + ty * 4];
            ull b2[4];
            {
                const ull* pb0 = (const ull*)&Bs[kk][tx * 4];
                const ull* pb1 = (const ull*)&Bs[kk][64 + tx * 4];
                b2[0] = pb0[0]; b2[1] = pb0[1];
                b2[2] = pb1[0]; b2[3] = pb1[1];
            }
            ull ad[8];
#pragma unroll
            for (int i = 0; i < 8; i++) ad[i] = dup2(a[i]);
#pragma unroll
            for (int i = 0; i < 8; i++)
#pragma unroll
                for (int p = 0; p < 4; p++)
                    acc2[i][p] = ffma2(ad[i], b2[p], acc2[i][p]);
        }
        __syncthreads();
    }

#pragma unroll
    for (int i = 0; i < 8; i++) {
        const int r = m0 + ((i < 4) ? (ty * 4 + i) : (64 + ty * 4 + (i - 4)));
        const float bv = bias[r];
        const float2 c0 = unpack2(acc2[i][0]), c1 = unpack2(acc2[i][1]);
        const float2 c2 = unpack2(acc2[i][2]), c3 = unpack2(acc2[i][3]);
        float4 v0, v1;
        v0.x = fmaxf(c0.x + bv, 0.0f); v0.y = fmaxf(c0.y + bv, 0.0f);
        v0.z = fmaxf(c1.x + bv, 0.0f); v0.w = fmaxf(c1.y + bv, 0.0f);
        v1.x = fmaxf(c2.x + bv, 0.0f); v1.y = fmaxf(c2.y + bv, 0.0f);
        v1.z = fmaxf(c3.x + bv, 0.0f); v1.w = fmaxf(c3.y + bv, 0.0f);
        *(float4*)(Yb + (size_t)r * N + n0 + tx * 4)      = v0;
        *(float4*)(Yb + (size_t)r * N + n0 + 64 + tx * 4) = v1;
    }
}

// =================================================================
// global max over N per (b, channel) of gf
// =================================================================
__global__ __launch_bounds__(128) void rowmax_kernel(const float* __restrict__ gf,
                                                     float* __restrict__ out)
{
    const int o = blockIdx.x, b = blockIdx.y;
    const float* row = gf + ((size_t)b * 1024 + o) * NPTS;
    float m = -3.0e38f;
    for (int i = threadIdx.x; i < NPTS; i += 128) m = fmaxf(m, row[i]);
#pragma unroll
    for (int off = 16; off > 0; off >>= 1) m = fmaxf(m, __shfl_xor_sync(0xffffffffu, m, off));
    __shared__ float smx[4];
    if ((threadIdx.x & 31) == 0) smx[threadIdx.x >> 5] = m;
    __syncthreads();
    if (threadIdx.x == 0)
        out[(size_t)b * 1024 + o] = fmaxf(fmaxf(smx[0], smx[1]), fmaxf(smx[2], smx[3]));
}

// =================================================================
extern "C" void kernel_launch(void* const* d_in, const int* in_sizes, int n_in,
                              void* d_out, int out_size)
{
    const float* x   = (const float*)d_in[0];
    const float* sW0 = (const float*)d_in[1];
    const float* sb0 = (const float*)d_in[2];
    const float* sW1 = (const float*)d_in[3];
    const float* sb1 = (const float*)d_in[4];
    const float* sW2 = (const float*)d_in[5];
    const float* sb2 = (const float*)d_in[6];
    const float* gW0 = (const float*)d_in[7];
    const float* gb0 = (const float*)d_in[8];
    const float* gW1 = (const float*)d_in[9];
    const float* gb1 = (const float*)d_in[10];
    const float* mW0 = (const float*)d_in[11];
    const float* mb0 = (const float*)d_in[12];
    const float* mW1 = (const float*)d_in[13];
    const float* mb1 = (const float*)d_in[14];

    const int B = in_sizes[0] / (3 * NPTS);
    float* out = (float*)d_out;

    void *p_idx, *p_feat, *p_point, *p_gf0, *p_gf, *p_msf0;
    cudaGetSymbolAddress(&p_idx,   g_idx);
    cudaGetSymbolAddress(&p_feat,  g_feat);
    cudaGetSymbolAddress(&p_point, g_point);
    cudaGetSymbolAddress(&p_gf0,   g_gf0);
    cudaGetSymbolAddress(&p_gf,    g_gf);
    cudaGetSymbolAddress(&p_msf0,  g_msf0);

    cudaFuncSetAttribute(feat_kernel,
                         cudaFuncAttributeMaxDynamicSharedMemorySize, SMEM_FEAT_BYTES);

    // 1) KNN
    knn_kernel<<<dim3(NPTS / 8, B), 256>>>(x, (int*)p_idx);

    // 2) per-point MLP features
    feat_kernel<<<dim3(NPTS / 128, 3, B), 128, SMEM_FEAT_BYTES>>>(
        x, sW0, sb0, sW1, sb1, sW2, sb2, (float*)p_feat, B);

    // 3) gather-max -> point[B,384,N]
    maxpool_kernel<<<dim3(NPTS / 8, 3, B), 256>>>(
        (const float*)p_feat, (const int*)p_idx, (float*)p_point, B);

    // 4) gf0 = relu(gW0 @ point + gb0)
    gemm_bias_relu<<<dim3(NPTS / 128, 256 / 128, B), 256>>>(
        gW0, gb0, (const float*)p_point, (float*)p_gf0, 256, 384);

    // 5) gf = relu(gW1 @ gf0 + gb1)
    gemm_bias_relu<<<dim3(NPTS / 128, 1024 / 128, B), 256>>>(
        gW1, gb1, (const float*)p_gf0, (float*)p_gf, 1024, 256);

    // 6) global_feature
    rowmax_kernel<<<dim3(1024, B), 128>>>((const float*)p_gf, out);

    // 7) msf0 = relu(mW0 @ gf + mb0)
    gemm_bias_relu<<<dim3(NPTS / 128, 256 / 128, B), 256>>>(
        mW0, mb0, (const float*)p_gf, (float*)p_msf0, 256, 1024);

    // 8) msf = relu(mW1 @ msf0 + mb1)
    gemm_bias_relu<<<dim3(NPTS / 128, 128 / 128, B), 256>>>(
        mW1, mb1, (const float*)p_msf0, out + (size_t)B * 1024, 128, 256);
}